// round 1
// baseline (speedup 1.0000x reference)
#include <cuda_runtime.h>
#include <math.h>

// Causal self-attention, B=4, S=4096, D=64, fp32.
// Flash-attention style: one q-row per thread, online softmax, K/V tiles
// staged in shared memory and read as warp-uniform float4 broadcasts.

#define BM 64          // q rows per CTA (== threads per CTA)
#define BN 64          // k rows per tile
#define DH 64          // head dim
#define NTHREADS 64
#define NV4 (DH / 4)   // 16 float4 per row

__device__ __forceinline__ float ex2_approx(float x) {
    float y;
    asm("ex2.approx.f32 %0, %1;" : "=f"(y) : "f"(x));
    return y;
}

__global__ __launch_bounds__(NTHREADS)
void fa_causal_kernel(const float* __restrict__ Q,
                      const float* __restrict__ K,
                      const float* __restrict__ V,
                      float* __restrict__ O,
                      int B, int S) {
    __shared__ float Ks[BN * DH];
    __shared__ float Vs[BN * DH];

    const int num_qt = S / BM;                 // 64
    const int idx = blockIdx.x;
    const int b   = idx % B;
    const int qt  = num_qt - 1 - (idx / B);    // heavy tiles first
    const int tid = threadIdx.x;
    const int r   = qt * BM + tid;             // this thread's q row

    // q row pre-scaled into log2-softmax domain: (1/sqrt(D)) * log2(e)
    const float scale = 0.125f * 1.44269504088896340736f;
    const float4* qptr = reinterpret_cast<const float4*>(
        Q + ((size_t)b * S + r) * DH);

    float4 q4[NV4];
#pragma unroll
    for (int i = 0; i < NV4; i++) {
        float4 v = qptr[i];
        v.x *= scale; v.y *= scale; v.z *= scale; v.w *= scale;
        q4[i] = v;
    }

    float4 o4[NV4];
#pragma unroll
    for (int i = 0; i < NV4; i++) o4[i] = make_float4(0.f, 0.f, 0.f, 0.f);

    float m = -INFINITY;
    float l = 0.f;

    for (int kt = 0; kt <= qt; kt++) {
        // --- cooperative tile load: K and V, 64x64 fp32 each, coalesced float4
        const float4* kbase = reinterpret_cast<const float4*>(
            K + ((size_t)b * S + (size_t)kt * BN) * DH);
        const float4* vbase = reinterpret_cast<const float4*>(
            V + ((size_t)b * S + (size_t)kt * BN) * DH);
        float4* ks4 = reinterpret_cast<float4*>(Ks);
        float4* vs4 = reinterpret_cast<float4*>(Vs);
#pragma unroll
        for (int i = 0; i < (BN * DH / 4) / NTHREADS; i++) {   // 16 iters
            int e = i * NTHREADS + tid;
            ks4[e] = kbase[e];
            vs4[e] = vbase[e];
        }
        __syncthreads();

        // diagonal tile: row r only sees k <= r  ->  j <= tid
        const int jmax = (kt == qt) ? (tid + 1) : BN;

        for (int j = 0; j < jmax; j++) {
            const float4* krow = reinterpret_cast<const float4*>(Ks + j * DH);
            // dot(q, K[j]) with 4 independent accumulators (ILP)
            float sx = 0.f, sy = 0.f, sz = 0.f, sw = 0.f;
#pragma unroll
            for (int i = 0; i < NV4; i++) {
                float4 kk = krow[i];
                sx = fmaf(q4[i].x, kk.x, sx);
                sy = fmaf(q4[i].y, kk.y, sy);
                sz = fmaf(q4[i].z, kk.z, sz);
                sw = fmaf(q4[i].w, kk.w, sw);
            }
            float s = (sx + sy) + (sz + sw);   // already in log2 units

            // online softmax: rescale only when the running max moves
            float m_new = fmaxf(m, s);
            if (m_new > m) {
                float c = ex2_approx(m - m_new);
                l *= c;
#pragma unroll
                for (int i = 0; i < NV4; i++) {
                    o4[i].x *= c; o4[i].y *= c; o4[i].z *= c; o4[i].w *= c;
                }
                m = m_new;
            }
            float p = ex2_approx(s - m);
            l += p;

            const float4* vrow = reinterpret_cast<const float4*>(Vs + j * DH);
#pragma unroll
            for (int i = 0; i < NV4; i++) {
                float4 vv = vrow[i];
                o4[i].x = fmaf(p, vv.x, o4[i].x);
                o4[i].y = fmaf(p, vv.y, o4[i].y);
                o4[i].z = fmaf(p, vv.z, o4[i].z);
                o4[i].w = fmaf(p, vv.w, o4[i].w);
            }
        }
        __syncthreads();
    }

    const float inv_l = 1.f / l;
    float4* optr = reinterpret_cast<float4*>(O + ((size_t)b * S + r) * DH);
#pragma unroll
    for (int i = 0; i < NV4; i++) {
        float4 v = o4[i];
        v.x *= inv_l; v.y *= inv_l; v.z *= inv_l; v.w *= inv_l;
        optr[i] = v;
    }
}

extern "C" void kernel_launch(void* const* d_in, const int* in_sizes, int n_in,
                              void* d_out, int out_size) {
    const float* Q = (const float*)d_in[0];
    const float* K = (const float*)d_in[1];
    const float* V = (const float*)d_in[2];
    float* O = (float*)d_out;

    const int B = 4, S = 4096;
    const int grid = B * (S / BM);   // 256 CTAs
    fa_causal_kernel<<<grid, NTHREADS>>>(Q, K, V, O, B, S);
}